// round 1
// baseline (speedup 1.0000x reference)
#include <cuda_runtime.h>

#define SS 2048
#define RR 384

// Scratch (no allocations allowed — device globals per harness rules)
__device__ float g_kv[RR * SS * 16];     // [r][s][k0..7, v0..7]  ~50MB
__device__ float g_bias[RR * SS];        // 1e9*(mask-1)
__device__ float g_qpart[RR * 16 * 72];  // per-(r, s-chunk) partial masked sums (+count at [64])
__device__ float g_o[RR * 64];           // attention output per r, flattened [h*8+c]

// ---------------------------------------------------------------------------
// Kernel A: LayerNorm + k/v projection + deterministic masked-query partials
// grid (16, 384), 256 threads; each block: fixed r, 128 s-rows (warp does 16)
// ---------------------------------------------------------------------------
__global__ __launch_bounds__(256) void kernelA(
    const float* __restrict__ M, const float* __restrict__ Mmask,
    const float* __restrict__ ln_g, const float* __restrict__ ln_b,
    const float* __restrict__ Wk, const float* __restrict__ Wv)
{
    __shared__ float sWkv[64 * 16];
    __shared__ float sg[64], sb[64];
    __shared__ float sbuf[8][64];
    __shared__ float qpw[8][72];
    const int tid = threadIdx.x, w = tid >> 5, t = tid & 31;
    const int r = blockIdx.y, s0 = blockIdx.x * 128;

    if (tid < 64) { sg[tid] = ln_g[tid]; sb[tid] = ln_b[tid]; }
    for (int i = tid; i < 1024; i += 256) {
        int d = i >> 4, c = i & 15;
        sWkv[i] = (c < 8) ? Wk[d * 8 + c] : Wv[d * 8 + c - 8];
    }
    __syncthreads();

    float q0 = 0.f, q1 = 0.f, cnt = 0.f;
    for (int it = 0; it < 16; ++it) {
        int s = s0 + w + 8 * it;
        const float* row = M + ((s * RR) + r) * 64;
        float a = row[t], b = row[t + 32];
        float sum = a + b, sq = a * a + b * b;
        #pragma unroll
        for (int o = 16; o > 0; o >>= 1) {
            sum += __shfl_xor_sync(0xffffffffu, sum, o);
            sq  += __shfl_xor_sync(0xffffffffu, sq,  o);
        }
        float mu   = sum * (1.f / 64.f);
        float var  = sq * (1.f / 64.f) - mu * mu;
        float rstd = rsqrtf(var + 1e-5f);
        float h0 = (a - mu) * rstd * sg[t]      + sb[t];
        float h1 = (b - mu) * rstd * sg[t + 32] + sb[t + 32];
        sbuf[w][t] = h0; sbuf[w][t + 32] = h1;
        float mk = 0.f;
        if (t == 0) mk = Mmask[s * RR + r];
        mk = __shfl_sync(0xffffffffu, mk, 0);
        __syncwarp();
        // 16 dot products (k0..7, v0..7): lane pairs split the d-range
        int oo = t & 15, dbase = (t < 16) ? 0 : 32;
        float acc = 0.f;
        #pragma unroll
        for (int d = 0; d < 32; ++d)
            acc += sbuf[w][dbase + d] * sWkv[(dbase + d) * 16 + oo];
        acc += __shfl_down_sync(0xffffffffu, acc, 16);
        if (t < 16) g_kv[((r * SS) + s) * 16 + t] = acc;
        if (t == 0) g_bias[r * SS + s] = 1e9f * (mk - 1.f);
        q0 += mk * h0; q1 += mk * h1; cnt += mk;
        __syncwarp();
    }
    qpw[w][t] = q0; qpw[w][t + 32] = q1;
    if (t == 0) qpw[w][64] = cnt;
    __syncthreads();
    if (tid < 65) {
        float acc = 0.f;
        #pragma unroll
        for (int ww = 0; ww < 8; ++ww) acc += qpw[ww][tid];
        g_qpart[(r * 16 + blockIdx.x) * 72 + tid] = acc;
    }
}

// ---------------------------------------------------------------------------
// Kernel B: per-r pooled q, logits, softmax over S, o[r][8][8]
// grid (384), 256 threads, 64KB dynamic smem for logits [8][2048]
// ---------------------------------------------------------------------------
__global__ __launch_bounds__(256) void kernelB(const float* __restrict__ Wq)
{
    extern __shared__ float slog[];  // 8 * 2048 floats
    __shared__ float sqa[65];
    __shared__ float sq[64];
    const int tid = threadIdx.x, r = blockIdx.x;

    if (tid < 65) {
        float a = 0.f;
        #pragma unroll
        for (int c = 0; c < 16; ++c) a += g_qpart[(r * 16 + c) * 72 + tid];
        sqa[tid] = a;
    }
    __syncthreads();
    if (tid < 64) sqa[tid] = sqa[tid] / (sqa[64] + 1e-10f);
    __syncthreads();
    if (tid < 64) {
        float acc = 0.f;
        #pragma unroll
        for (int d = 0; d < 64; ++d) acc += sqa[d] * Wq[d * 64 + tid];
        sq[tid] = acc * 0.35355339059327373f;  // * C^-0.5
    }
    __syncthreads();

    for (int s = tid; s < SS; s += 256) {
        const float4* kp = (const float4*)&g_kv[((r * SS) + s) * 16];
        float4 k0 = kp[0], k1 = kp[1];
        float bias = g_bias[r * SS + s];
        #pragma unroll
        for (int h = 0; h < 8; ++h) {
            float lg = bias
                + sq[h * 8 + 0] * k0.x + sq[h * 8 + 1] * k0.y
                + sq[h * 8 + 2] * k0.z + sq[h * 8 + 3] * k0.w
                + sq[h * 8 + 4] * k1.x + sq[h * 8 + 5] * k1.y
                + sq[h * 8 + 6] * k1.z + sq[h * 8 + 7] * k1.w;
            slog[h * SS + s] = lg;
        }
    }
    __syncthreads();

    const int w = tid >> 5, t = tid & 31;  // warp w owns head h = w
    float mx = -3.0e38f;
    for (int s = t; s < SS; s += 32) mx = fmaxf(mx, slog[w * SS + s]);
    #pragma unroll
    for (int o = 16; o > 0; o >>= 1) mx = fmaxf(mx, __shfl_xor_sync(0xffffffffu, mx, o));
    float Z = 0.f;
    for (int s = t; s < SS; s += 32) {
        float e = __expf(slog[w * SS + s] - mx);
        slog[w * SS + s] = e; Z += e;
    }
    #pragma unroll
    for (int o = 16; o > 0; o >>= 1) Z += __shfl_xor_sync(0xffffffffu, Z, o);
    float acc[8] = {0.f, 0.f, 0.f, 0.f, 0.f, 0.f, 0.f, 0.f};
    for (int s = t; s < SS; s += 32) {
        float wt = slog[w * SS + s];
        const float4* vp = (const float4*)&g_kv[((r * SS) + s) * 16 + 8];
        float4 v0 = vp[0], v1 = vp[1];
        acc[0] += wt * v0.x; acc[1] += wt * v0.y; acc[2] += wt * v0.z; acc[3] += wt * v0.w;
        acc[4] += wt * v1.x; acc[5] += wt * v1.y; acc[6] += wt * v1.z; acc[7] += wt * v1.w;
    }
    float inv = 1.f / Z;
    #pragma unroll
    for (int c = 0; c < 8; ++c) {
        float v = acc[c];
        #pragma unroll
        for (int o = 16; o > 0; o >>= 1) v += __shfl_xor_sync(0xffffffffu, v, o);
        if (t == 0) g_o[r * 64 + w * 8 + c] = v * inv;
    }
}

// ---------------------------------------------------------------------------
// Kernel C (hot): LN recompute + gate GEMV + output GEMV + residual
// grid (32, 384), 256 threads; warp processes 8 s-rows at once
// smem: WgT[64][68], WpT[64][68] (o-scaled Wo^T), row buffers [8][8][64]
// ---------------------------------------------------------------------------
__global__ __launch_bounds__(256) void kernelC(
    const float* __restrict__ M,
    const float* __restrict__ Wg, const float* __restrict__ bgv,
    const float* __restrict__ Wo, const float* __restrict__ bov,
    const float* __restrict__ ln_g, const float* __restrict__ ln_b,
    float* __restrict__ outp)
{
    extern __shared__ float dyn[];
    float* sWgT = dyn;              // [64][68]: WgT[j][d] = Wg[d][j]
    float* sWpT = dyn + 64 * 68;    // [64][68]: WpT[d][j] = o[j]*Wo[j][d]
    float* sBuf = dyn + 2 * 64 * 68;// [8 warps][8 rows][64]
    __shared__ float sg[64], sb[64], sbg[64], sbo[64], so[64];
    const int tid = threadIdx.x, w = tid >> 5, t = tid & 31;
    const int r = blockIdx.y, s0 = blockIdx.x * 64 + w * 8;

    if (tid < 64) {
        sg[tid] = ln_g[tid]; sb[tid] = ln_b[tid];
        sbg[tid] = bgv[tid]; sbo[tid] = bov[tid];
        so[tid] = g_o[r * 64 + tid];
    }
    __syncthreads();
    for (int i = tid; i < 4096; i += 256) {        // coalesced read of Wg
        int dd = i >> 6, jj = i & 63;
        sWgT[jj * 68 + dd] = Wg[dd * 64 + jj];
    }
    for (int i = tid; i < 4096; i += 256) {        // coalesced read of Wo
        int jj = i >> 6, dd = i & 63;
        sWpT[dd * 68 + jj] = so[jj] * Wo[jj * 64 + dd];
    }
    __syncthreads();

    float* buf = sBuf + w * 512;
    float m0[8], m1[8];
    #pragma unroll
    for (int rr = 0; rr < 8; ++rr) {
        const float* row = M + (((s0 + rr) * RR) + r) * 64;
        float a = row[t], b = row[t + 32];
        m0[rr] = a; m1[rr] = b;
        float sum = a + b, sq = a * a + b * b;
        #pragma unroll
        for (int o = 16; o > 0; o >>= 1) {
            sum += __shfl_xor_sync(0xffffffffu, sum, o);
            sq  += __shfl_xor_sync(0xffffffffu, sq,  o);
        }
        float mu = sum * (1.f / 64.f);
        float rstd = rsqrtf(sq * (1.f / 64.f) - mu * mu + 1e-5f);
        buf[rr * 64 + t]      = (a - mu) * rstd * sg[t]      + sb[t];
        buf[rr * 64 + t + 32] = (b - mu) * rstd * sg[t + 32] + sb[t + 32];
    }
    __syncwarp();

    // gate phase: thread owns j = t and j = t+32
    float ag0[8], ag1[8];
    {
        float b0 = sbg[t], b1 = sbg[t + 32];
        #pragma unroll
        for (int rr = 0; rr < 8; ++rr) { ag0[rr] = b0; ag1[rr] = b1; }
    }
    const float4* W0 = (const float4*)&sWgT[t * 68];
    const float4* W1 = (const float4*)&sWgT[(t + 32) * 68];
    #pragma unroll 4
    for (int dd = 0; dd < 16; ++dd) {
        float4 w0 = W0[dd], w1 = W1[dd];
        #pragma unroll
        for (int rr = 0; rr < 8; ++rr) {
            float4 mh = *(const float4*)&buf[rr * 64 + dd * 4];
            ag0[rr] += mh.x * w0.x + mh.y * w0.y + mh.z * w0.z + mh.w * w0.w;
            ag1[rr] += mh.x * w1.x + mh.y * w1.y + mh.z * w1.z + mh.w * w1.w;
        }
    }
    __syncwarp();
    #pragma unroll
    for (int rr = 0; rr < 8; ++rr) {
        buf[rr * 64 + t]      = 1.f / (1.f + __expf(-ag0[rr]));
        buf[rr * 64 + t + 32] = 1.f / (1.f + __expf(-ag1[rr]));
    }
    __syncwarp();

    // output phase: thread owns d = t and d = t+32
    float ao0[8], ao1[8];
    {
        float b0 = sbo[t], b1 = sbo[t + 32];
        #pragma unroll
        for (int rr = 0; rr < 8; ++rr) { ao0[rr] = b0; ao1[rr] = b1; }
    }
    const float4* P0 = (const float4*)&sWpT[t * 68];
    const float4* P1 = (const float4*)&sWpT[(t + 32) * 68];
    #pragma unroll 4
    for (int jj = 0; jj < 16; ++jj) {
        float4 w0 = P0[jj], w1 = P1[jj];
        #pragma unroll
        for (int rr = 0; rr < 8; ++rr) {
            float4 gg = *(const float4*)&buf[rr * 64 + jj * 4];
            ao0[rr] += gg.x * w0.x + gg.y * w0.y + gg.z * w0.z + gg.w * w0.w;
            ao1[rr] += gg.x * w1.x + gg.y * w1.y + gg.z * w1.z + gg.w * w1.w;
        }
    }
    #pragma unroll
    for (int rr = 0; rr < 8; ++rr) {
        float* orow = outp + (((s0 + rr) * RR) + r) * 64;
        orow[t]      = m0[rr] + ao0[rr];
        orow[t + 32] = m1[rr] + ao1[rr];
    }
}

// ---------------------------------------------------------------------------
extern "C" void kernel_launch(void* const* d_in, const int* in_sizes, int n_in,
                              void* d_out, int out_size)
{
    (void)in_sizes; (void)n_in; (void)out_size;
    const float* M    = (const float*)d_in[0];
    const float* mask = (const float*)d_in[1];
    const float* ln_g = (const float*)d_in[2];
    const float* ln_b = (const float*)d_in[3];
    const float* Wq   = (const float*)d_in[4];
    const float* Wk   = (const float*)d_in[5];
    const float* Wv   = (const float*)d_in[6];
    const float* Wg   = (const float*)d_in[7];
    const float* bg   = (const float*)d_in[8];
    const float* Wo   = (const float*)d_in[9];
    const float* bo   = (const float*)d_in[10];
    float* outp = (float*)d_out;

    const int smemB = 8 * SS * 4;                       // 65536 B
    const int smemC = (2 * 64 * 68 + 8 * 8 * 64) * 4;   // 51200 B
    cudaFuncSetAttribute(kernelB, cudaFuncAttributeMaxDynamicSharedMemorySize, smemB);
    cudaFuncSetAttribute(kernelC, cudaFuncAttributeMaxDynamicSharedMemorySize, smemC);

    kernelA<<<dim3(16, 384), 256>>>(M, mask, ln_g, ln_b, Wk, Wv);
    kernelB<<<384, 256, smemB>>>(Wq);
    kernelC<<<dim3(32, 384), 256, smemC>>>(M, Wg, bg, Wo, bo, ln_g, ln_b, outp);
}

// round 2
// speedup vs baseline: 1.1673x; 1.1673x over previous
#include <cuda_runtime.h>

#define SS 2048
#define RR 384

// ---- device scratch (no allocs allowed) ----
__device__ float g_kv[RR * 16 * SS];     // [r][c][s]; c: 0-7 = k, 8-15 = v
__device__ float g_maskT[RR * SS];       // transposed mask [r][s]
__device__ float g_qpart[RR * 16 * 68];  // per-(r, s-block) partials: 64 P[d], Pmu, Pc
__device__ float g_o[RR * 64];           // attention output per r  [h*8+c]
// LN-folded weights (kernel P)
__device__ float g_AW[16 * 64];          // [c][d] = g[d]*Wkv[d][c]
__device__ float g_S1kv[16];
__device__ float g_bkv[16];
__device__ float g_GW[64 * 64];          // [j][d] = g[d]*Wg[d][j]
__device__ float g_S1g[64];
__device__ float g_bG[64];               // bg[j] + sum_d b[d]*Wg[d][j]
__device__ float g_WoT[64 * 64];         // [d][j] = Wo[j][d]

// ---- packed fp32x2 helpers (Blackwell FFMA2) ----
__device__ __forceinline__ unsigned long long ffma2(unsigned long long a,
                                                    unsigned long long b,
                                                    unsigned long long c) {
    unsigned long long d;
    asm("fma.rn.f32x2 %0, %1, %2, %3;" : "=l"(d) : "l"(a), "l"(b), "l"(c));
    return d;
}
__device__ __forceinline__ float2 upk(unsigned long long v) {
    float2 f; asm("mov.b64 {%0,%1}, %2;" : "=f"(f.x), "=f"(f.y) : "l"(v)); return f;
}
__device__ __forceinline__ unsigned long long pk2(float lo, float hi) {
    unsigned long long r; asm("mov.b64 %0, {%1,%2};" : "=l"(r) : "f"(lo), "f"(hi)); return r;
}

// ---------------------------------------------------------------------------
// Kernel D: transpose mask [S][R] -> [R][S]
// ---------------------------------------------------------------------------
__global__ __launch_bounds__(256) void kernelD(const float* __restrict__ Mmask) {
    __shared__ float t[32][33];
    const int tx = threadIdx.x & 31, ty = threadIdx.x >> 5;  // ty 0..7
    const int r0 = blockIdx.x * 32, s0 = blockIdx.y * 32;
    #pragma unroll
    for (int k = 0; k < 32; k += 8)
        t[ty + k][tx] = Mmask[(s0 + ty + k) * RR + r0 + tx];
    __syncthreads();
    #pragma unroll
    for (int k = 0; k < 32; k += 8)
        g_maskT[(r0 + ty + k) * SS + s0 + tx] = t[tx][ty + k];
}

// ---------------------------------------------------------------------------
// Kernel P: fold LayerNorm gamma/beta into all weight matrices (tiny, once)
// ---------------------------------------------------------------------------
__global__ __launch_bounds__(256) void kernelP(
    const float* __restrict__ lng, const float* __restrict__ lnb,
    const float* __restrict__ Wk, const float* __restrict__ Wv,
    const float* __restrict__ Wg, const float* __restrict__ bg,
    const float* __restrict__ Wo)
{
    const int tid = threadIdx.x;
    for (int i = tid; i < 16 * 64; i += 256) {
        int c = i >> 6, d = i & 63;
        float w = (c < 8) ? Wk[d * 8 + c] : Wv[d * 8 + c - 8];
        g_AW[i] = lng[d] * w;
    }
    for (int i = tid; i < 64 * 64; i += 256) {
        int a = i >> 6, b = i & 63;
        g_GW[i]  = lng[b] * Wg[b * 64 + a];   // [j=a][d=b]
        g_WoT[i] = Wo[b * 64 + a];            // [d=a][j=b]
    }
    __syncthreads();
    if (tid < 16) {
        float s1 = 0.f, bb = 0.f;
        for (int d = 0; d < 64; ++d) {
            s1 += g_AW[tid * 64 + d];
            float w = (tid < 8) ? Wk[d * 8 + tid] : Wv[d * 8 + tid - 8];
            bb += lnb[d] * w;
        }
        g_S1kv[tid] = s1; g_bkv[tid] = bb;
    }
    if (tid >= 64 && tid < 128) {
        int j = tid - 64;
        float s1 = 0.f, bb = 0.f;
        for (int d = 0; d < 64; ++d) {
            s1 += g_GW[j * 64 + d];
            bb += lnb[d] * Wg[d * 64 + j];
        }
        g_S1g[j] = s1; g_bG[j] = bg[j] + bb;
    }
}

// ---------------------------------------------------------------------------
// Kernel A: rows-in-lanes LN (folded) + k/v projection + masked-q partials
// grid (16, 384), 128 threads; each thread owns one (s,r) row
// ---------------------------------------------------------------------------
__global__ __launch_bounds__(128) void kernelA(const float* __restrict__ M) {
    __shared__ __align__(16) float stage[4][32][68];
    __shared__ __align__(16) float sAW[16][68];
    __shared__ float sS1[16], sbk[16];
    __shared__ float sQ[4][68];
    const int tid = threadIdx.x, w = tid >> 5, t = tid & 31;
    const int r = blockIdx.y;
    const int srow = blockIdx.x * 128 + w * 32;

    for (int i = tid; i < 16 * 64; i += 128) { int c = i >> 6, d = i & 63; sAW[c][d] = g_AW[i]; }
    if (tid < 16) { sS1[tid] = g_S1kv[tid]; sbk[tid] = g_bkv[tid]; }
    __syncthreads();

    const int cr = t >> 4, cc = (t & 15) * 4;
    #pragma unroll
    for (int i = 0; i < 16; ++i) {
        int rr = i * 2 + cr;
        *(float4*)&stage[w][rr][cc] =
            *(const float4*)&M[(((srow + rr) * RR) + r) * 64 + cc];
    }
    __syncwarp();

    unsigned long long xp[32];
    {
        const ulonglong2* rp = (const ulonglong2*)&stage[w][t][0];
        #pragma unroll
        for (int i = 0; i < 16; ++i) { ulonglong2 v = rp[i]; xp[2 * i] = v.x; xp[2 * i + 1] = v.y; }
    }
    float sum = 0.f, sq = 0.f;
    #pragma unroll
    for (int i = 0; i < 32; ++i) { float2 f = upk(xp[i]); sum += f.x + f.y; sq += f.x * f.x + f.y * f.y; }
    const float mu = sum * (1.f / 64.f);
    const float rstd = rsqrtf(sq * (1.f / 64.f) - mu * mu + 1e-5f);
    const int s = srow + t;
    const float mk = g_maskT[r * SS + s];

    // k/v projection (LN folded)
    #pragma unroll
    for (int c = 0; c < 16; ++c) {
        const ulonglong2* wp_ = (const ulonglong2*)&sAW[c][0];
        unsigned long long a0 = 0ull, a1 = 0ull;
        #pragma unroll
        for (int i = 0; i < 16; ++i) {
            ulonglong2 v = wp_[i];
            a0 = ffma2(xp[2 * i], v.x, a0);
            a1 = ffma2(xp[2 * i + 1], v.y, a1);
        }
        float2 f0 = upk(a0), f1 = upk(a1);
        float dot = f0.x + f0.y + f1.x + f1.y;
        g_kv[((r * 16 + c) * SS) + s] = rstd * (dot - mu * sS1[c]) + sbk[c];
    }

    // masked-query partial rows -> reuse tile, then column-reduce
    {
        const float mkr = mk * rstd;
        const unsigned long long mp = pk2(mkr, mkr);
        float4* qr = (float4*)&stage[w][t][0];
        #pragma unroll
        for (int i = 0; i < 16; ++i) {
            float2 a = upk(ffma2(xp[2 * i], mp, 0ull));
            float2 b = upk(ffma2(xp[2 * i + 1], mp, 0ull));
            qr[i] = make_float4(a.x, a.y, b.x, b.y);
        }
        stage[w][t][64] = mkr * mu;  // Pmu contribution
        stage[w][t][65] = mk;        // Pc contribution
    }
    __syncwarp();
    {
        float ax = 0.f, ay = 0.f;
        #pragma unroll
        for (int rr = 0; rr < 32; ++rr) {
            float2 v = *(const float2*)&stage[w][rr][2 * t];
            ax += v.x; ay += v.y;
        }
        sQ[w][2 * t] = ax; sQ[w][2 * t + 1] = ay;
        if (t < 2) {
            float e = 0.f;
            #pragma unroll
            for (int rr = 0; rr < 32; ++rr) e += stage[w][rr][64 + t];
            sQ[w][64 + t] = e;
        }
    }
    __syncthreads();
    if (tid < 66) {
        float a = sQ[0][tid] + sQ[1][tid] + sQ[2][tid] + sQ[3][tid];
        g_qpart[(r * 16 + blockIdx.x) * 68 + tid] = a;
    }
}

// ---------------------------------------------------------------------------
// Kernel B: pooled q, logits, softmax over S, o[r][8][8]
// ---------------------------------------------------------------------------
__global__ __launch_bounds__(256) void kernelB(
    const float* __restrict__ Wq, const float* __restrict__ lng,
    const float* __restrict__ lnb)
{
    extern __shared__ float slog[];  // 8 * 2048
    __shared__ float sqa[68];
    __shared__ float sq[64];
    const int tid = threadIdx.x, r = blockIdx.x;

    if (tid < 66) {
        float a = 0.f;
        #pragma unroll
        for (int c = 0; c < 16; ++c) a += g_qpart[(r * 16 + c) * 68 + tid];
        sqa[tid] = a;
    }
    __syncthreads();
    if (tid < 64) {
        float Pmu = sqa[64], Pc = sqa[65];
        sqa[tid] = (lng[tid] * (sqa[tid] - Pmu) + lnb[tid] * Pc) / (Pc + 1e-10f);
    }
    __syncthreads();
    if (tid < 64) {
        float acc = 0.f;
        #pragma unroll
        for (int d = 0; d < 64; ++d) acc += sqa[d] * Wq[d * 64 + tid];
        sq[tid] = acc * 0.35355339059327373f;  // * C^-0.5
    }
    __syncthreads();

    for (int s = tid; s < SS; s += 256) {
        float kk[8];
        #pragma unroll
        for (int c = 0; c < 8; ++c) kk[c] = g_kv[((r * 16 + c) * SS) + s];
        float bias = 1e9f * (g_maskT[r * SS + s] - 1.f);
        #pragma unroll
        for (int h = 0; h < 8; ++h) {
            float lg = bias;
            #pragma unroll
            for (int c = 0; c < 8; ++c) lg += sq[h * 8 + c] * kk[c];
            slog[h * SS + s] = lg;
        }
    }
    __syncthreads();

    const int w = tid >> 5, t = tid & 31;  // warp w owns head h = w
    float mx = -3.0e38f;
    for (int s = t; s < SS; s += 32) mx = fmaxf(mx, slog[w * SS + s]);
    #pragma unroll
    for (int o = 16; o > 0; o >>= 1) mx = fmaxf(mx, __shfl_xor_sync(0xffffffffu, mx, o));
    float Z = 0.f;
    for (int s = t; s < SS; s += 32) {
        float e = __expf(slog[w * SS + s] - mx);
        slog[w * SS + s] = e; Z += e;
    }
    #pragma unroll
    for (int o = 16; o > 0; o >>= 1) Z += __shfl_xor_sync(0xffffffffu, Z, o);
    float acc[8] = {0.f, 0.f, 0.f, 0.f, 0.f, 0.f, 0.f, 0.f};
    for (int s = t; s < SS; s += 32) {
        float wt = slog[w * SS + s];
        #pragma unroll
        for (int c = 0; c < 8; ++c) acc[c] += wt * g_kv[((r * 16 + 8 + c) * SS) + s];
    }
    float inv = 1.f / Z;
    #pragma unroll
    for (int c = 0; c < 8; ++c) {
        float v = acc[c];
        #pragma unroll
        for (int o = 16; o > 0; o >>= 1) v += __shfl_xor_sync(0xffffffffu, v, o);
        if (t == 0) g_o[r * 64 + w * 8 + c] = v * inv;
    }
}

// ---------------------------------------------------------------------------
// Kernel C (hot): rows-in-lanes, folded-LN gate GEMV + output GEMV, FFMA2
// grid (4, 384), 128 threads; 4 subtiles of 128 rows per block
// ---------------------------------------------------------------------------
__global__ __launch_bounds__(128) void kernelC(
    const float* __restrict__ M, const float* __restrict__ bo,
    float* __restrict__ outp)
{
    extern __shared__ __align__(16) float dyn[];
    float* stage = dyn;                     // [4][32][68]
    float* sGW   = dyn + 4 * 32 * 68;       // [64][68]
    float* sWoT  = sGW + 64 * 68;           // [64][68]
    float* so    = sWoT + 64 * 68;          // [64]
    float* sS1g  = so + 64;                 // [64]
    float* sbG   = sS1g + 64;               // [64]
    float* sbo   = sbG + 64;                // [64]
    const int tid = threadIdx.x, w = tid >> 5, t = tid & 31;
    const int r = blockIdx.y;

    for (int i = tid; i < 4096; i += 128) {
        int j = i >> 6, d = i & 63;
        sGW[j * 68 + d]  = g_GW[i];
        sWoT[j * 68 + d] = g_WoT[i];
    }
    if (tid < 64) {
        so[tid] = g_o[r * 64 + tid];
        sS1g[tid] = g_S1g[tid]; sbG[tid] = g_bG[tid]; sbo[tid] = bo[tid];
    }
    __syncthreads();

    float* tile = stage + w * 32 * 68;
    const int cr = t >> 4, cc = (t & 15) * 4;

    for (int sub = 0; sub < 4; ++sub) {
        const int srow = blockIdx.x * 512 + sub * 128 + w * 32;
        #pragma unroll
        for (int i = 0; i < 16; ++i) {
            int rr = i * 2 + cr;
            *(float4*)&tile[rr * 68 + cc] =
                *(const float4*)&M[(((srow + rr) * RR) + r) * 64 + cc];
        }
        __syncwarp();

        unsigned long long xp[32];
        {
            const ulonglong2* rp = (const ulonglong2*)&tile[t * 68];
            #pragma unroll
            for (int i = 0; i < 16; ++i) { ulonglong2 v = rp[i]; xp[2 * i] = v.x; xp[2 * i + 1] = v.y; }
        }
        float sum = 0.f, sq = 0.f;
        #pragma unroll
        for (int i = 0; i < 32; ++i) { float2 f = upk(xp[i]); sum += f.x + f.y; sq += f.x * f.x + f.y * f.y; }
        const float mu = sum * (1.f / 64.f);
        const float rstd = rsqrtf(sq * (1.f / 64.f) - mu * mu + 1e-5f);

        // gate: g[j] = sigmoid(rstd*(x.GW[j] - mu*S1g[j]) + bG[j]); ghat = g*o
        unsigned long long gp[32];
        #pragma unroll
        for (int jp = 0; jp < 32; ++jp) {
            const ulonglong2* wa = (const ulonglong2*)&sGW[(2 * jp) * 68];
            const ulonglong2* wb = (const ulonglong2*)&sGW[(2 * jp + 1) * 68];
            unsigned long long a0 = 0ull, a1 = 0ull, b0 = 0ull, b1 = 0ull;
            #pragma unroll
            for (int i = 0; i < 16; ++i) {
                ulonglong2 va = wa[i], vb = wb[i];
                a0 = ffma2(xp[2 * i], va.x, a0); a1 = ffma2(xp[2 * i + 1], va.y, a1);
                b0 = ffma2(xp[2 * i], vb.x, b0); b1 = ffma2(xp[2 * i + 1], vb.y, b1);
            }
            float2 fa0 = upk(a0), fa1 = upk(a1), fb0 = upk(b0), fb1 = upk(b1);
            float da = fa0.x + fa0.y + fa1.x + fa1.y;
            float db = fb0.x + fb0.y + fb1.x + fb1.y;
            float aga = rstd * (da - mu * sS1g[2 * jp])     + sbG[2 * jp];
            float agb = rstd * (db - mu * sS1g[2 * jp + 1]) + sbG[2 * jp + 1];
            float ga = 1.f / (1.f + __expf(-aga));
            float gb = 1.f / (1.f + __expf(-agb));
            float2 oo = *(const float2*)&so[2 * jp];
            gp[jp] = pk2(ga * oo.x, gb * oo.y);
        }

        // out[d] = sum_j ghat[j]*Wo[j][d] + bo[d] + x[d]
        #pragma unroll
        for (int dp = 0; dp < 32; ++dp) {
            const ulonglong2* wa = (const ulonglong2*)&sWoT[(2 * dp) * 68];
            const ulonglong2* wb = (const ulonglong2*)&sWoT[(2 * dp + 1) * 68];
            unsigned long long a0 = 0ull, a1 = 0ull, b0 = 0ull, b1 = 0ull;
            #pragma unroll
            for (int i = 0; i < 16; ++i) {
                ulonglong2 va = wa[i], vb = wb[i];
                a0 = ffma2(gp[2 * i], va.x, a0); a1 = ffma2(gp[2 * i + 1], va.y, a1);
                b0 = ffma2(gp[2 * i], vb.x, b0); b1 = ffma2(gp[2 * i + 1], vb.y, b1);
            }
            float2 fa0 = upk(a0), fa1 = upk(a1), fb0 = upk(b0), fb1 = upk(b1);
            float2 xr = upk(xp[dp]);
            float o0 = fa0.x + fa0.y + fa1.x + fa1.y + sbo[2 * dp]     + xr.x;
            float o1 = fb0.x + fb0.y + fb1.x + fb1.y + sbo[2 * dp + 1] + xr.y;
            *(float2*)&tile[t * 68 + 2 * dp] = make_float2(o0, o1);
        }
        __syncwarp();
        #pragma unroll
        for (int i = 0; i < 16; ++i) {
            int rr = i * 2 + cr;
            *(float4*)&outp[(((srow + rr) * RR) + r) * 64 + cc] =
                *(const float4*)&tile[rr * 68 + cc];
        }
        __syncwarp();
    }
}

// ---------------------------------------------------------------------------
extern "C" void kernel_launch(void* const* d_in, const int* in_sizes, int n_in,
                              void* d_out, int out_size)
{
    (void)in_sizes; (void)n_in; (void)out_size;
    const float* M    = (const float*)d_in[0];
    const float* mask = (const float*)d_in[1];
    const float* ln_g = (const float*)d_in[2];
    const float* ln_b = (const float*)d_in[3];
    const float* Wq   = (const float*)d_in[4];
    const float* Wk   = (const float*)d_in[5];
    const float* Wv   = (const float*)d_in[6];
    const float* Wg   = (const float*)d_in[7];
    const float* bg   = (const float*)d_in[8];
    const float* Wo   = (const float*)d_in[9];
    const float* bo   = (const float*)d_in[10];
    float* outp = (float*)d_out;

    const int smemB = 8 * SS * 4;                                    // 65536
    const int smemC = (4 * 32 * 68 + 2 * 64 * 68 + 4 * 64) * 4;      // 70656
    cudaFuncSetAttribute(kernelB, cudaFuncAttributeMaxDynamicSharedMemorySize, smemB);
    cudaFuncSetAttribute(kernelC, cudaFuncAttributeMaxDynamicSharedMemorySize, smemC);

    kernelD<<<dim3(12, 64), 256>>>(mask);
    kernelP<<<1, 256>>>(ln_g, ln_b, Wk, Wv, Wg, bg, Wo);
    kernelA<<<dim3(16, 384), 128>>>(M);
    kernelB<<<384, 256, smemB>>>(Wq, ln_g, ln_b);
    kernelC<<<dim3(4, 384), 128, smemC>>>(M, bo, outp);
}